// round 1
// baseline (speedup 1.0000x reference)
#include <cuda_runtime.h>
#include <math.h>

// Problem constants (fixed by the dataset)
#define BB   8
#define NN   4096
#define KNN  20
#define CO   64
#define M_EDGES (BB*NN*KNN)

#define K1_BLK  128
#define K1_GRID ((BB*NN)/K1_BLK)   // 256 blocks
#define TILE    1024               // candidate tile (float4 -> 16KB smem)

// Scratch (device globals: no runtime allocation allowed)
__device__ float4 g_pos4[BB*NN];           // x,y,z,|p|^2
__device__ float4 g_feat[BB*NN*KNN];       // dx,dy,dz,dist  (10.5 MB)
__device__ float  g_part[K1_GRID*14];      // per-block moment partials
__device__ float  g_A[CO*4];               // folded scale * W
__device__ float  g_C0[CO];                // folded bias

// ---------------------------------------------------------------------------
// Kernel 0: pack positions + squared norm
// ---------------------------------------------------------------------------
__global__ void prep_kernel(const float* __restrict__ pos) {
    int i = blockIdx.x * blockDim.x + threadIdx.x;
    if (i < BB*NN) {
        float x = pos[3*i+0], y = pos[3*i+1], z = pos[3*i+2];
        g_pos4[i] = make_float4(x, y, z, x*x + y*y + z*z);
    }
}

// ---------------------------------------------------------------------------
// Kernel 1: KNN (thread-per-point, register top-20) + edge features + moments
// ---------------------------------------------------------------------------
__global__ void knn_kernel() {
    __shared__ float4 sh[TILE];
    __shared__ float  red[14*K1_BLK];

    const int tid = threadIdx.x;
    const int gpt = blockIdx.x * K1_BLK + tid;   // global point id
    const int b   = gpt / NN;
    const int i   = gpt % NN;                    // index within batch

    const float4 pi = g_pos4[b*NN + i];

    float bd[KNN];
    int   bi[KNN];
#pragma unroll
    for (int s = 0; s < KNN; s++) { bd[s] = 1e30f; bi[s] = 0; }

    for (int t = 0; t < NN; t += TILE) {
        __syncthreads();
        for (int l = tid; l < TILE; l += K1_BLK)
            sh[l] = g_pos4[b*NN + t + l];
        __syncthreads();

#pragma unroll 4
        for (int j = 0; j < TILE; j++) {
            float4 p  = sh[j];
            float dot = pi.x*p.x + pi.y*p.y + pi.z*p.z;
            float d2  = (pi.w + p.w) - 2.0f*dot;   // matches reference formula
            int   jg  = t + j;
            if (jg == i) d2 = 1e30f;               // self-exclusion
            if (d2 < bd[KNN-1]) {
                bd[KNN-1] = d2; bi[KNN-1] = jg;
#pragma unroll
                for (int s = KNN-1; s > 0; --s) {
                    if (bd[s] < bd[s-1]) {
                        float td = bd[s]; bd[s] = bd[s-1]; bd[s-1] = td;
                        int   ti = bi[s]; bi[s] = bi[s-1]; bi[s-1] = ti;
                    }
                }
            }
        }
    }

    // Edge features + local moment accumulation
    float s0=0,s1=0,s2=0,s3=0;
    float pxx=0,pxy=0,pxz=0,pxw=0,pyy=0,pyz=0,pyw=0,pzz=0,pzw=0,pww=0;
#pragma unroll
    for (int s = 0; s < KNN; s++) {
        float4 pj = g_pos4[b*NN + bi[s]];
        float dx = pj.x - pi.x;
        float dy = pj.y - pi.y;
        float dz = pj.z - pi.z;
        float dist = sqrtf(dx*dx + dy*dy + dz*dz);  // recomputed like reference
        g_feat[gpt*KNN + s] = make_float4(dx, dy, dz, dist);
        s0 += dx; s1 += dy; s2 += dz; s3 += dist;
        pxx += dx*dx; pxy += dx*dy; pxz += dx*dz; pxw += dx*dist;
        pyy += dy*dy; pyz += dy*dz; pyw += dy*dist;
        pzz += dz*dz; pzw += dz*dist; pww += dist*dist;
    }

    float vals[14] = {s0,s1,s2,s3,pxx,pxy,pxz,pxw,pyy,pyz,pyw,pzz,pzw,pww};
#pragma unroll
    for (int c = 0; c < 14; c++) red[c*K1_BLK + tid] = vals[c];
    __syncthreads();

    // Deterministic fixed-order block reduction (14 threads, serial over block)
    if (tid < 14) {
        float acc = 0.0f;
        for (int l = 0; l < K1_BLK; l++) acc += red[tid*K1_BLK + l];
        g_part[blockIdx.x*14 + tid] = acc;
    }
}

// ---------------------------------------------------------------------------
// Kernel 2: fold BatchNorm into per-channel affine (deterministic, double)
// ---------------------------------------------------------------------------
__global__ void stats_kernel(const float* __restrict__ W,
                             const float* __restrict__ bias,
                             const float* __restrict__ gamma,
                             const float* __restrict__ beta) {
    __shared__ double mom[14];
    int tid = threadIdx.x;
    if (tid < 14) {
        double a = 0.0;
        for (int blk = 0; blk < K1_GRID; blk++)
            a += (double)g_part[blk*14 + tid];
        mom[tid] = a;
    }
    __syncthreads();
    if (tid < CO) {
        const double M = (double)M_EDGES;
        double m0=mom[0]/M, m1=mom[1]/M, m2=mom[2]/M, m3=mom[3]/M;
        double Sxx=mom[4]/M, Sxy=mom[5]/M, Sxz=mom[6]/M, Sxw=mom[7]/M;
        double Syy=mom[8]/M, Syz=mom[9]/M, Syw=mom[10]/M;
        double Szz=mom[11]/M, Szw=mom[12]/M, Sww=mom[13]/M;

        double w0 = W[tid*4+0], w1 = W[tid*4+1], w2 = W[tid*4+2], w3 = W[tid*4+3];
        double bb = bias[tid];
        double wm = w0*m0 + w1*m1 + w2*m2 + w3*m3;
        double mu = wm + bb;
        double E2 = w0*w0*Sxx + w1*w1*Syy + w2*w2*Szz + w3*w3*Sww
                  + 2.0*(w0*w1*Sxy + w0*w2*Sxz + w0*w3*Sxw
                       + w1*w2*Syz + w1*w3*Syw + w2*w3*Szw)
                  + 2.0*bb*wm + bb*bb;
        double var   = E2 - mu*mu;
        double scale = (double)gamma[tid] * rsqrt(var + 1e-5);
        g_A[tid*4+0] = (float)(scale * w0);
        g_A[tid*4+1] = (float)(scale * w1);
        g_A[tid*4+2] = (float)(scale * w2);
        g_A[tid*4+3] = (float)(scale * w3);
        g_C0[tid]    = (float)(scale * (bb - mu) + (double)beta[tid]);
    }
}

// ---------------------------------------------------------------------------
// Kernel 3: per-edge affine + relu + mean over k (4 points/block, 64 ch each)
// ---------------------------------------------------------------------------
__global__ void out_kernel(float* __restrict__ out) {
    __shared__ float4 shf[4*KNN];
    const int tid = threadIdx.x;
    const int pt0 = blockIdx.x * 4;

    for (int l = tid; l < 4*KNN; l += 256)
        shf[l] = g_feat[pt0*KNN + l];
    __syncthreads();

    const int lp = tid >> 6;    // local point 0..3
    const int c  = tid & 63;    // channel
    const float a0 = g_A[c*4+0], a1 = g_A[c*4+1], a2 = g_A[c*4+2], a3 = g_A[c*4+3];
    const float c0 = g_C0[c];

    float acc = 0.0f;
#pragma unroll
    for (int s = 0; s < KNN; s++) {
        float4 f = shf[lp*KNN + s];
        float v = a0*f.x + a1*f.y + a2*f.z + a3*f.w + c0;
        acc += fmaxf(v, 0.0f);   // relu; subsequent leaky(0.1) is identity on >=0
    }
    out[(size_t)(pt0 + lp)*CO + c] = acc * (1.0f / KNN);
}

// ---------------------------------------------------------------------------
extern "C" void kernel_launch(void* const* d_in, const int* in_sizes, int n_in,
                              void* d_out, int out_size) {
    const float* pos   = (const float*)d_in[1];
    const float* W     = (const float*)d_in[2];
    const float* bias  = (const float*)d_in[3];
    const float* gamma = (const float*)d_in[4];
    const float* beta  = (const float*)d_in[5];
    float* out = (float*)d_out;

    prep_kernel<<<(BB*NN + 255)/256, 256>>>(pos);
    knn_kernel<<<K1_GRID, K1_BLK>>>();
    stats_kernel<<<1, 64>>>(W, bias, gamma, beta);
    out_kernel<<<(BB*NN)/4, 256>>>(out);
}